// round 12
// baseline (speedup 1.0000x reference)
#include <cuda_runtime.h>
#include <cuda_bf16.h>
#include <cstdint>

#define N_NODES 100000
#define N_EDGES 1600000
#define HID 128
#define N_LAYERS 4

// ---------------------------------------------------------------------------
// Scratch (static __device__ — no allocations allowed)
// ---------------------------------------------------------------------------
__device__ alignas(16) float g_out[(size_t)N_NODES * HID];   // agg + x per layer
__device__ alignas(16) float g_x1[(size_t)N_NODES * HID];    // ping
__device__ alignas(16) float g_x2[(size_t)N_NODES * HID];    // pong
__device__ int   g_rowptr[N_NODES + 1];
__device__ int   g_cursor[N_NODES];
__device__ int   g_srcs[N_EDGES];
__device__ int   g_is64;
// per layer: 4 bf16 tiles [n][k] (transposed weights): W1hi, W1lo, W2hi, W2lo
__device__ alignas(16) __nv_bfloat16 g_w[(size_t)N_LAYERS * 4 * HID * HID];

// ---------------------------------------------------------------------------
// Warp-level mma.sync on registers (register operands only).
// ---------------------------------------------------------------------------
__device__ __forceinline__ void mma_bf16(float* c,
                                         uint32_t a0, uint32_t a1, uint32_t a2, uint32_t a3,
                                         uint32_t b0, uint32_t b1) {
    asm volatile("mma.sync.aligned.m16n8k16.row.col.f32.bf16.bf16.f32 "
                 "{%0,%1,%2,%3},{%4,%5,%6,%7},{%8,%9},{%0,%1,%2,%3};"
                 : "+f"(c[0]), "+f"(c[1]), "+f"(c[2]), "+f"(c[3])
                 : "r"(a0), "r"(a1), "r"(a2), "r"(a3), "r"(b0), "r"(b1));
}

// ---------------------------------------------------------------------------
// Edge-index dtype detection: JAX with x64 disabled silently makes int32
// despite dtype=jnp.int64 in the reference. For true int64 (values < 2^31),
// every odd 32-bit word is 0; for int32 data odd words are live indices.
// ---------------------------------------------------------------------------
__global__ void gin_detect_k(const int* ei32) {
    if (threadIdx.x == 0 && blockIdx.x == 0) {
        int zeros = 0;
        for (int i = 0; i < 256; i++)
            if (ei32[2 * i + 1] == 0) zeros++;
        g_is64 = (zeros > 200) ? 1 : 0;
    }
}

__device__ __forceinline__ int edge_val(const void* ei, long idx) {
    if (g_is64) return (int)((const long long*)ei)[idx];
    return ((const int*)ei)[idx];
}

// ---------------------------------------------------------------------------
// CSR build kernels (dst-sorted counting sort; no fp atomics anywhere)
// ---------------------------------------------------------------------------
__global__ void gin_zero_k() {
    int i = blockIdx.x * blockDim.x + threadIdx.x;
    if (i < N_NODES) g_cursor[i] = 0;
}

__global__ void gin_hist_k(const void* ei) {
    int e = blockIdx.x * blockDim.x + threadIdx.x;
    if (e < N_EDGES) {
        int d = edge_val(ei, (long)N_EDGES + e);
        if (d >= 0 && d < N_NODES) atomicAdd(&g_cursor[d], 1);
    }
}

__global__ void gin_scan_k() {
    const int T = 1024, SEG = (N_NODES + 1023) / 1024;  // 98
    __shared__ int part[T];
    int t = threadIdx.x;
    int s = 0;
    for (int j = 0; j < SEG; j++) {
        int i = t * SEG + j;
        if (i < N_NODES) s += g_cursor[i];
    }
    part[t] = s;
    __syncthreads();
    for (int off = 1; off < T; off <<= 1) {
        int v = (t >= off) ? part[t - off] : 0;
        __syncthreads();
        part[t] += v;
        __syncthreads();
    }
    int run = (t > 0) ? part[t - 1] : 0;
    for (int j = 0; j < SEG; j++) {
        int i = t * SEG + j;
        if (i < N_NODES) {
            int c = g_cursor[i];
            g_rowptr[i] = run;
            g_cursor[i] = run;
            run += c;
        }
    }
    if (t == T - 1) g_rowptr[N_NODES] = part[T - 1];
}

__global__ void gin_scatter_k(const void* ei) {
    int e = blockIdx.x * blockDim.x + threadIdx.x;
    if (e < N_EDGES) {
        int d = edge_val(ei, (long)N_EDGES + e);
        int s = edge_val(ei, e);
        if (d >= 0 && d < N_NODES && s >= 0 && s < N_NODES) {
            int pos = atomicAdd(&g_cursor[d], 1);
            if (pos >= 0 && pos < N_EDGES) g_srcs[pos] = s;
        }
    }
}

// ---------------------------------------------------------------------------
// Weight prep: split fp32 -> (hi, lo) bf16, transposed to [n][k]
// ---------------------------------------------------------------------------
__global__ void gin_prep_w(const float* W1, const float* W2) {
    int i = blockIdx.x * blockDim.x + threadIdx.x;
    if (i >= N_LAYERS * 2 * HID * HID) return;
    int l = i >> 15;          // 2*128*128 = 32768 per layer
    int m = (i >> 14) & 1;    // 0 = W1, 1 = W2
    int k = (i >> 7) & 127;   // input dim
    int n = i & 127;          // output dim
    float w = (m == 0 ? W1 : W2)[(size_t)l * HID * HID + k * HID + n];
    __nv_bfloat16 hi = __float2bfloat16(w);
    __nv_bfloat16 lo = __float2bfloat16(w - __bfloat162float(hi));
    size_t base = ((size_t)l * 4 + m * 2) * (HID * HID) + (size_t)n * HID + k;
    g_w[base] = hi;
    g_w[base + (size_t)HID * HID] = lo;
}

// ---------------------------------------------------------------------------
// Aggregation: out[i] = x[i] + sum_{j in N(i)} x[j]   (warp per node, no
// atomics). 8-wide unrolled gather: 8 warp-uniform index loads + 8
// independent float4 gathers in flight per iteration (MLP ~16), two FADD
// chains so the adds never gate load issue.
// ---------------------------------------------------------------------------
__device__ __forceinline__ const float* sel_x(int sel, const float* x0) {
    return sel == 0 ? x0 : (sel == 1 ? g_x1 : g_x2);
}

__global__ void gin_agg_k(const float* x0, int insel) {
    const float* x = sel_x(insel, x0);
    int node = (blockIdx.x * blockDim.x + threadIdx.x) >> 5;
    int lane = threadIdx.x & 31;
    if (node >= N_NODES) return;
    int beg = g_rowptr[node];
    int end = g_rowptr[node + 1];
    const float4* x4 = reinterpret_cast<const float4*>(x);
    float4 acc = x4[(size_t)node * 32 + lane];
    float4 accB = make_float4(0.f, 0.f, 0.f, 0.f);
    int j = beg;
    for (; j + 8 <= end; j += 8) {
        int s0 = g_srcs[j + 0], s1 = g_srcs[j + 1];
        int s2 = g_srcs[j + 2], s3 = g_srcs[j + 3];
        int s4 = g_srcs[j + 4], s5 = g_srcs[j + 5];
        int s6 = g_srcs[j + 6], s7 = g_srcs[j + 7];
        float4 v0 = x4[(size_t)s0 * 32 + lane];
        float4 v1 = x4[(size_t)s1 * 32 + lane];
        float4 v2 = x4[(size_t)s2 * 32 + lane];
        float4 v3 = x4[(size_t)s3 * 32 + lane];
        float4 v4 = x4[(size_t)s4 * 32 + lane];
        float4 v5 = x4[(size_t)s5 * 32 + lane];
        float4 v6 = x4[(size_t)s6 * 32 + lane];
        float4 v7 = x4[(size_t)s7 * 32 + lane];
        acc.x += v0.x;  acc.y += v0.y;  acc.z += v0.z;  acc.w += v0.w;
        accB.x += v1.x; accB.y += v1.y; accB.z += v1.z; accB.w += v1.w;
        acc.x += v2.x;  acc.y += v2.y;  acc.z += v2.z;  acc.w += v2.w;
        accB.x += v3.x; accB.y += v3.y; accB.z += v3.z; accB.w += v3.w;
        acc.x += v4.x;  acc.y += v4.y;  acc.z += v4.z;  acc.w += v4.w;
        accB.x += v5.x; accB.y += v5.y; accB.z += v5.z; accB.w += v5.w;
        acc.x += v6.x;  acc.y += v6.y;  acc.z += v6.z;  acc.w += v6.w;
        accB.x += v7.x; accB.y += v7.y; accB.z += v7.z; accB.w += v7.w;
    }
    if (j + 4 <= end) {
        int s0 = g_srcs[j + 0], s1 = g_srcs[j + 1];
        int s2 = g_srcs[j + 2], s3 = g_srcs[j + 3];
        float4 v0 = x4[(size_t)s0 * 32 + lane];
        float4 v1 = x4[(size_t)s1 * 32 + lane];
        float4 v2 = x4[(size_t)s2 * 32 + lane];
        float4 v3 = x4[(size_t)s3 * 32 + lane];
        acc.x += v0.x;  acc.y += v0.y;  acc.z += v0.z;  acc.w += v0.w;
        accB.x += v1.x; accB.y += v1.y; accB.z += v1.z; accB.w += v1.w;
        acc.x += v2.x;  acc.y += v2.y;  acc.z += v2.z;  acc.w += v2.w;
        accB.x += v3.x; accB.y += v3.y; accB.z += v3.z; accB.w += v3.w;
        j += 4;
    }
    for (; j < end; j++) {
        int s = g_srcs[j];
        float4 v = x4[(size_t)s * 32 + lane];
        acc.x += v.x; acc.y += v.y; acc.z += v.z; acc.w += v.w;
    }
    acc.x += accB.x; acc.y += accB.y; acc.z += accB.z; acc.w += accB.w;
    reinterpret_cast<float4*>(g_out)[(size_t)node * 32 + lane] = acc;
}

// ---------------------------------------------------------------------------
// Fused MLP: x_out = x_in + relu(relu(g_out @ W1 + b1) @ W2 + b2)
// 128-row tile per CTA, 256 threads / 8 warps; warp w owns rows [16w,16w+16).
// Split-bf16 3-term GEMMs via mma.sync.m16n8k16; all smem loads via one plain
// word pointer derived from the extern __shared__ symbol.
// ---------------------------------------------------------------------------
#define PITCH 136                    // bf16/row (68 words; 68 mod 32 = 4 -> conflict-free)
#define PITCHW 68                    // uint32 words per row
#define TILE_E (128 * PITCH)         // bf16 elems per tile
#define TILE_W (TILE_E / 2)          // words per tile
#define SM_TOTAL (6 * TILE_E * 2)    // 208896 bytes

__device__ __forceinline__ void gemm128(float (*acc)[4], uint32_t* smw,
                                        int oAh, int oAl, int oBh, int oBl,
                                        int w, int l) {
    const int g4 = l >> 2;       // 0..7
    const int t4 = l & 3;        // 0..3
    const int rowA = (w << 4) + g4;
    #pragma unroll
    for (int k0 = 0; k0 < 128; k0 += 16) {
        const int kw = (k0 >> 1) + t4;   // word offset of this lane's k-pair
        const int ia = rowA * PITCHW + kw;
        uint32_t ah0 = smw[oAh + ia];
        uint32_t ah1 = smw[oAh + ia + 8 * PITCHW];
        uint32_t ah2 = smw[oAh + ia + 4];
        uint32_t ah3 = smw[oAh + ia + 8 * PITCHW + 4];
        uint32_t al0 = smw[oAl + ia];
        uint32_t al1 = smw[oAl + ia + 8 * PITCHW];
        uint32_t al2 = smw[oAl + ia + 4];
        uint32_t al3 = smw[oAl + ia + 8 * PITCHW + 4];
        #pragma unroll
        for (int nt2 = 0; nt2 < 8; nt2++) {
            const int n0 = (nt2 << 4) + g4;           // n row in [n][k] tile
            const int ib = n0 * PITCHW + kw;
            uint32_t bh0 = smw[oBh + ib];
            uint32_t bh1 = smw[oBh + ib + 4];
            uint32_t bh2 = smw[oBh + ib + 8 * PITCHW];
            uint32_t bh3 = smw[oBh + ib + 8 * PITCHW + 4];
            mma_bf16(acc[2 * nt2],     ah0, ah1, ah2, ah3, bh0, bh1);
            mma_bf16(acc[2 * nt2 + 1], ah0, ah1, ah2, ah3, bh2, bh3);
            mma_bf16(acc[2 * nt2],     al0, al1, al2, al3, bh0, bh1);
            mma_bf16(acc[2 * nt2 + 1], al0, al1, al2, al3, bh2, bh3);
            uint32_t bl0 = smw[oBl + ib];
            uint32_t bl1 = smw[oBl + ib + 4];
            uint32_t bl2 = smw[oBl + ib + 8 * PITCHW];
            uint32_t bl3 = smw[oBl + ib + 8 * PITCHW + 4];
            mma_bf16(acc[2 * nt2],     ah0, ah1, ah2, ah3, bl0, bl1);
            mma_bf16(acc[2 * nt2 + 1], ah0, ah1, ah2, ah3, bl2, bl3);
        }
    }
}

__global__ void __launch_bounds__(256, 1) gin_mlp_k(
    const float* x0, float* dout,
    const float* b1, const float* b2,
    int layer, int insel, int outsel)
{
    extern __shared__ __align__(16) __nv_bfloat16 sm[];
    __nv_bfloat16* sAh = sm;                 // tile 0
    __nv_bfloat16* sAl = sm + TILE_E;        // tile 1
    __nv_bfloat16* sW  = sm + 2 * TILE_E;    // tiles 2..5: W1hi, W1lo, W2hi, W2lo

    int tid = threadIdx.x, w = tid >> 5, l = tid & 31;
    long tile = (long)blockIdx.x * 128;

    const float* xres = sel_x(insel, x0);
    float* xout = (outsel == 3) ? dout : (outsel == 1 ? g_x1 : g_x2);
    const __nv_bfloat16* wt = g_w + (size_t)layer * 4 * HID * HID;

    // Load 4 weight tiles ([n][k] bf16) into pitched smem (16B chunks)
    for (int i = tid; i < 4 * 128 * 16; i += 256) {
        int t = i >> 11;
        int r = (i >> 4) & 127;
        int c = (i & 15) << 3;
        uint4 v = *reinterpret_cast<const uint4*>(wt + ((size_t)t << 14) + (r << 7) + c);
        *reinterpret_cast<uint4*>(sW + t * TILE_E + r * PITCH + c) = v;
    }

    // Load activation tile, split fp32 -> hi/lo bf16
    for (int i = tid; i < 128 * 16; i += 256) {
        int r = i >> 4;
        int c = (i & 15) << 3;
        long g = tile + r;
        float vv[8];
        if (g < N_NODES) {
            const float4* p = reinterpret_cast<const float4*>(g_out + g * HID + c);
            float4 v0 = p[0], v1 = p[1];
            vv[0] = v0.x; vv[1] = v0.y; vv[2] = v0.z; vv[3] = v0.w;
            vv[4] = v1.x; vv[5] = v1.y; vv[6] = v1.z; vv[7] = v1.w;
        } else {
            #pragma unroll
            for (int j = 0; j < 8; j++) vv[j] = 0.0f;
        }
        union { unsigned short s[8]; uint4 q; } ph, pl;
        #pragma unroll
        for (int j = 0; j < 8; j++) {
            __nv_bfloat16 h = __float2bfloat16(vv[j]);
            __nv_bfloat16 lo = __float2bfloat16(vv[j] - __bfloat162float(h));
            ph.s[j] = *reinterpret_cast<unsigned short*>(&h);
            pl.s[j] = *reinterpret_cast<unsigned short*>(&lo);
        }
        *reinterpret_cast<uint4*>(sAh + r * PITCH + c) = ph.q;
        *reinterpret_cast<uint4*>(sAl + r * PITCH + c) = pl.q;
    }
    __syncthreads();

    uint32_t* smw = reinterpret_cast<uint32_t*>(sm);  // plain: no const, no restrict

    float acc[16][4];
    #pragma unroll
    for (int i = 0; i < 16; i++)
        #pragma unroll
        for (int j = 0; j < 4; j++) acc[i][j] = 0.0f;

    // GEMM1: agg @ W1   (A = tiles 0/1, B = tiles 2/3)
    gemm128(acc, smw, 0, TILE_W, 2 * TILE_W, 3 * TILE_W, w, l);
    __syncthreads();  // all warps done reading sA before overwrite

    // Epilogue 1: h = relu(acc + b1) -> split back into sAh/sAl
    {
        int row0 = (w << 4) + (l >> 2);
        int cbase = (l & 3) << 1;
        #pragma unroll
        for (int nt = 0; nt < 16; nt++) {
            int col = (nt << 3) + cbase;
            float bb0 = b1[col], bb1 = b1[col + 1];
            float v0 = fmaxf(acc[nt][0] + bb0, 0.0f);
            float v1 = fmaxf(acc[nt][1] + bb1, 0.0f);
            float v2 = fmaxf(acc[nt][2] + bb0, 0.0f);
            float v3 = fmaxf(acc[nt][3] + bb1, 0.0f);
            __nv_bfloat16 h0 = __float2bfloat16(v0), h1 = __float2bfloat16(v1);
            __nv_bfloat16 h2 = __float2bfloat16(v2), h3 = __float2bfloat16(v3);
            __nv_bfloat16 l0 = __float2bfloat16(v0 - __bfloat162float(h0));
            __nv_bfloat16 l1 = __float2bfloat16(v1 - __bfloat162float(h1));
            __nv_bfloat16 l2 = __float2bfloat16(v2 - __bfloat162float(h2));
            __nv_bfloat16 l3 = __float2bfloat16(v3 - __bfloat162float(h3));
            smw[row0 * PITCHW + (col >> 1)] =
                (uint32_t)*reinterpret_cast<unsigned short*>(&h0) |
                ((uint32_t)*reinterpret_cast<unsigned short*>(&h1) << 16);
            smw[(row0 + 8) * PITCHW + (col >> 1)] =
                (uint32_t)*reinterpret_cast<unsigned short*>(&h2) |
                ((uint32_t)*reinterpret_cast<unsigned short*>(&h3) << 16);
            smw[TILE_W + row0 * PITCHW + (col >> 1)] =
                (uint32_t)*reinterpret_cast<unsigned short*>(&l0) |
                ((uint32_t)*reinterpret_cast<unsigned short*>(&l1) << 16);
            smw[TILE_W + (row0 + 8) * PITCHW + (col >> 1)] =
                (uint32_t)*reinterpret_cast<unsigned short*>(&l2) |
                ((uint32_t)*reinterpret_cast<unsigned short*>(&l3) << 16);
        }
    }
    __syncthreads();

    #pragma unroll
    for (int i = 0; i < 16; i++)
        #pragma unroll
        for (int j = 0; j < 4; j++) acc[i][j] = 0.0f;

    // GEMM2: h @ W2   (A = tiles 0/1, B = tiles 4/5)
    gemm128(acc, smw, 0, TILE_W, 4 * TILE_W, 5 * TILE_W, w, l);

    // Epilogue 2: x_out = x_in + relu(acc + b2)
    {
        int row0 = (w << 4) + (l >> 2);
        int cbase = (l & 3) << 1;
        long g0 = tile + row0;
        long g1 = g0 + 8;
        #pragma unroll
        for (int nt = 0; nt < 16; nt++) {
            int col = (nt << 3) + cbase;
            float bb0 = b2[col], bb1 = b2[col + 1];
            if (g0 < N_NODES) {
                float2 xr = *reinterpret_cast<const float2*>(xres + g0 * HID + col);
                float2 o;
                o.x = xr.x + fmaxf(acc[nt][0] + bb0, 0.0f);
                o.y = xr.y + fmaxf(acc[nt][1] + bb1, 0.0f);
                *reinterpret_cast<float2*>(xout + g0 * HID + col) = o;
            }
            if (g1 < N_NODES) {
                float2 xr = *reinterpret_cast<const float2*>(xres + g1 * HID + col);
                float2 o;
                o.x = xr.x + fmaxf(acc[nt][2] + bb0, 0.0f);
                o.y = xr.y + fmaxf(acc[nt][3] + bb1, 0.0f);
                *reinterpret_cast<float2*>(xout + g1 * HID + col) = o;
            }
        }
    }
}

// ---------------------------------------------------------------------------
// Launch
// ---------------------------------------------------------------------------
extern "C" void kernel_launch(void* const* d_in, const int* in_sizes, int n_in,
                              void* d_out, int out_size) {
    const float* x  = (const float*)d_in[0];
    const void*  ei = d_in[1];                 // int32 or int64, detected on device
    const float* W1 = (const float*)d_in[2];
    const float* b1 = (const float*)d_in[3];
    const float* W2 = (const float*)d_in[4];
    const float* b2 = (const float*)d_in[5];
    float* out = (float*)d_out;

    cudaFuncSetAttribute(gin_mlp_k, cudaFuncAttributeMaxDynamicSharedMemorySize, SM_TOTAL);

    // dtype detection + weight split + CSR build (once per call)
    gin_detect_k<<<1, 32>>>((const int*)ei);
    gin_prep_w<<<(N_LAYERS * 2 * HID * HID + 255) / 256, 256>>>(W1, W2);
    gin_zero_k<<<(N_NODES + 255) / 256, 256>>>();
    gin_hist_k<<<(N_EDGES + 255) / 256, 256>>>(ei);
    gin_scan_k<<<1, 1024>>>();
    gin_scatter_k<<<(N_EDGES + 255) / 256, 256>>>(ei);

    const int agg_blocks = (N_NODES * 32 + 255) / 256;
    const int mlp_blocks = (N_NODES + 127) / 128;

    // layer schedule: insel -> outsel:  x->g_x1, g_x1->g_x2, g_x2->g_x1, g_x1->d_out
    const int ins[N_LAYERS]  = {0, 1, 2, 1};
    const int outs[N_LAYERS] = {1, 2, 1, 3};

    for (int l = 0; l < N_LAYERS; l++) {
        gin_agg_k<<<agg_blocks, 256>>>(x, ins[l]);
        gin_mlp_k<<<mlp_blocks, 256, SM_TOTAL>>>(x, out,
                                                 b1 + l * HID, b2 + l * HID,
                                                 l, ins[l], outs[l]);
    }
}

// round 15
// speedup vs baseline: 1.3649x; 1.3649x over previous
#include <cuda_runtime.h>
#include <cuda_bf16.h>
#include <cstdint>

#define N_NODES 100000
#define N_EDGES 1600000
#define HID 128
#define N_LAYERS 4

// ---------------------------------------------------------------------------
// Scratch (static __device__ — no allocations allowed)
// ---------------------------------------------------------------------------
__device__ alignas(16) float g_out[(size_t)N_NODES * HID];   // agg + x per layer
__device__ alignas(16) float g_x1[(size_t)N_NODES * HID];    // ping
__device__ alignas(16) float g_x2[(size_t)N_NODES * HID];    // pong
__device__ int   g_rowptr[N_NODES + 1];
__device__ int   g_cursor[N_NODES];
__device__ int   g_srcs[N_EDGES];
__device__ int   g_is64;
// per layer: 4 bf16 tiles [n][k] (transposed weights): W1hi, W1lo, W2hi, W2lo
__device__ alignas(16) __nv_bfloat16 g_w[(size_t)N_LAYERS * 4 * HID * HID];

// ---------------------------------------------------------------------------
// Warp-level mma.sync on registers (register operands only).
// ---------------------------------------------------------------------------
__device__ __forceinline__ void mma_bf16(float* c,
                                         uint32_t a0, uint32_t a1, uint32_t a2, uint32_t a3,
                                         uint32_t b0, uint32_t b1) {
    asm volatile("mma.sync.aligned.m16n8k16.row.col.f32.bf16.bf16.f32 "
                 "{%0,%1,%2,%3},{%4,%5,%6,%7},{%8,%9},{%0,%1,%2,%3};"
                 : "+f"(c[0]), "+f"(c[1]), "+f"(c[2]), "+f"(c[3])
                 : "r"(a0), "r"(a1), "r"(a2), "r"(a3), "r"(b0), "r"(b1));
}

// ---------------------------------------------------------------------------
// Edge-index dtype detection: JAX with x64 disabled silently makes int32
// despite dtype=jnp.int64 in the reference. For true int64 (values < 2^31),
// every odd 32-bit word is 0; for int32 data odd words are live indices.
// ---------------------------------------------------------------------------
__global__ void gin_detect_k(const int* ei32) {
    if (threadIdx.x == 0 && blockIdx.x == 0) {
        int zeros = 0;
        for (int i = 0; i < 256; i++)
            if (ei32[2 * i + 1] == 0) zeros++;
        g_is64 = (zeros > 200) ? 1 : 0;
    }
}

__device__ __forceinline__ int edge_val(const void* ei, long idx) {
    if (g_is64) return (int)((const long long*)ei)[idx];
    return ((const int*)ei)[idx];
}

// ---------------------------------------------------------------------------
// CSR build kernels (dst-sorted counting sort; no fp atomics anywhere)
// ---------------------------------------------------------------------------
__global__ void gin_zero_k() {
    int i = blockIdx.x * blockDim.x + threadIdx.x;
    if (i < N_NODES) g_cursor[i] = 0;
}

__global__ void gin_hist_k(const void* ei) {
    int e = blockIdx.x * blockDim.x + threadIdx.x;
    if (e < N_EDGES) {
        int d = edge_val(ei, (long)N_EDGES + e);
        if (d >= 0 && d < N_NODES) atomicAdd(&g_cursor[d], 1);
    }
}

__global__ void gin_scan_k() {
    const int T = 1024, SEG = (N_NODES + 1023) / 1024;  // 98
    __shared__ int part[T];
    int t = threadIdx.x;
    int s = 0;
    for (int j = 0; j < SEG; j++) {
        int i = t * SEG + j;
        if (i < N_NODES) s += g_cursor[i];
    }
    part[t] = s;
    __syncthreads();
    for (int off = 1; off < T; off <<= 1) {
        int v = (t >= off) ? part[t - off] : 0;
        __syncthreads();
        part[t] += v;
        __syncthreads();
    }
    int run = (t > 0) ? part[t - 1] : 0;
    for (int j = 0; j < SEG; j++) {
        int i = t * SEG + j;
        if (i < N_NODES) {
            int c = g_cursor[i];
            g_rowptr[i] = run;
            g_cursor[i] = run;
            run += c;
        }
    }
    if (t == T - 1) g_rowptr[N_NODES] = part[T - 1];
}

__global__ void gin_scatter_k(const void* ei) {
    int e = blockIdx.x * blockDim.x + threadIdx.x;
    if (e < N_EDGES) {
        int d = edge_val(ei, (long)N_EDGES + e);
        int s = edge_val(ei, e);
        if (d >= 0 && d < N_NODES && s >= 0 && s < N_NODES) {
            int pos = atomicAdd(&g_cursor[d], 1);
            if (pos >= 0 && pos < N_EDGES) g_srcs[pos] = s;
        }
    }
}

// ---------------------------------------------------------------------------
// Weight prep: split fp32 -> (hi, lo) bf16, transposed to [n][k]
// ---------------------------------------------------------------------------
__global__ void gin_prep_w(const float* W1, const float* W2) {
    int i = blockIdx.x * blockDim.x + threadIdx.x;
    if (i >= N_LAYERS * 2 * HID * HID) return;
    int l = i >> 15;          // 2*128*128 = 32768 per layer
    int m = (i >> 14) & 1;    // 0 = W1, 1 = W2
    int k = (i >> 7) & 127;   // input dim
    int n = i & 127;          // output dim
    float w = (m == 0 ? W1 : W2)[(size_t)l * HID * HID + k * HID + n];
    __nv_bfloat16 hi = __float2bfloat16(w);
    __nv_bfloat16 lo = __float2bfloat16(w - __bfloat162float(hi));
    size_t base = ((size_t)l * 4 + m * 2) * (HID * HID) + (size_t)n * HID + k;
    g_w[base] = hi;
    g_w[base + (size_t)HID * HID] = lo;
}

// ---------------------------------------------------------------------------
// Aggregation: out[i] = x[i] + sum_{j in N(i)} x[j]   (warp per node, no
// atomics). R10 batch structure (one index load per lane per 32 edges,
// shfl-distributed) + 4-wide software pipeline: 4 independent float4
// gathers in flight per warp (8 warps x 4 LDG x 4 lines = 128 < 248 ->
// no L1tex wavefront-queue overflow), two FADD chains off the load path.
// ---------------------------------------------------------------------------
__device__ __forceinline__ const float* sel_x(int sel, const float* x0) {
    return sel == 0 ? x0 : (sel == 1 ? g_x1 : g_x2);
}

__global__ void gin_agg_k(const float* x0, int insel) {
    const float* x = sel_x(insel, x0);
    int node = (blockIdx.x * blockDim.x + threadIdx.x) >> 5;
    int lane = threadIdx.x & 31;
    if (node >= N_NODES) return;
    int beg = g_rowptr[node];
    int end = g_rowptr[node + 1];
    const float4* x4 = reinterpret_cast<const float4*>(x);
    float4 accA = x4[(size_t)node * 32 + lane];
    float4 accB = make_float4(0.f, 0.f, 0.f, 0.f);
    for (int j = beg; j < end; j += 32) {
        int n = end - j;
        if (n > 32) n = 32;
        int my = (lane < n) ? g_srcs[j + lane] : 0;
        int t = 0;
        for (; t + 4 <= n; t += 4) {
            int s0 = __shfl_sync(0xFFFFFFFFu, my, t);
            int s1 = __shfl_sync(0xFFFFFFFFu, my, t + 1);
            int s2 = __shfl_sync(0xFFFFFFFFu, my, t + 2);
            int s3 = __shfl_sync(0xFFFFFFFFu, my, t + 3);
            float4 v0 = x4[(size_t)s0 * 32 + lane];
            float4 v1 = x4[(size_t)s1 * 32 + lane];
            float4 v2 = x4[(size_t)s2 * 32 + lane];
            float4 v3 = x4[(size_t)s3 * 32 + lane];
            accA.x += v0.x; accA.y += v0.y; accA.z += v0.z; accA.w += v0.w;
            accB.x += v1.x; accB.y += v1.y; accB.z += v1.z; accB.w += v1.w;
            accA.x += v2.x; accA.y += v2.y; accA.z += v2.z; accA.w += v2.w;
            accB.x += v3.x; accB.y += v3.y; accB.z += v3.z; accB.w += v3.w;
        }
        for (; t < n; t++) {
            int s = __shfl_sync(0xFFFFFFFFu, my, t);
            float4 v = x4[(size_t)s * 32 + lane];
            accA.x += v.x; accA.y += v.y; accA.z += v.z; accA.w += v.w;
        }
    }
    accA.x += accB.x; accA.y += accB.y; accA.z += accB.z; accA.w += accB.w;
    reinterpret_cast<float4*>(g_out)[(size_t)node * 32 + lane] = accA;
}

// ---------------------------------------------------------------------------
// Fused MLP: x_out = x_in + relu(relu(g_out @ W1 + b1) @ W2 + b2)
// 128-row tile per CTA, 256 threads / 8 warps; warp w owns rows [16w,16w+16).
// Split-bf16 3-term GEMMs via mma.sync.m16n8k16; all smem loads via one plain
// word pointer derived from the extern __shared__ symbol.
// ---------------------------------------------------------------------------
#define PITCH 136                    // bf16/row (68 words; 68 mod 32 = 4 -> conflict-free)
#define PITCHW 68                    // uint32 words per row
#define TILE_E (128 * PITCH)         // bf16 elems per tile
#define TILE_W (TILE_E / 2)          // words per tile
#define SM_TOTAL (6 * TILE_E * 2)    // 208896 bytes

__device__ __forceinline__ void gemm128(float (*acc)[4], uint32_t* smw,
                                        int oAh, int oAl, int oBh, int oBl,
                                        int w, int l) {
    const int g4 = l >> 2;       // 0..7
    const int t4 = l & 3;        // 0..3
    const int rowA = (w << 4) + g4;
    #pragma unroll
    for (int k0 = 0; k0 < 128; k0 += 16) {
        const int kw = (k0 >> 1) + t4;   // word offset of this lane's k-pair
        const int ia = rowA * PITCHW + kw;
        uint32_t ah0 = smw[oAh + ia];
        uint32_t ah1 = smw[oAh + ia + 8 * PITCHW];
        uint32_t ah2 = smw[oAh + ia + 4];
        uint32_t ah3 = smw[oAh + ia + 8 * PITCHW + 4];
        uint32_t al0 = smw[oAl + ia];
        uint32_t al1 = smw[oAl + ia + 8 * PITCHW];
        uint32_t al2 = smw[oAl + ia + 4];
        uint32_t al3 = smw[oAl + ia + 8 * PITCHW + 4];
        #pragma unroll
        for (int nt2 = 0; nt2 < 8; nt2++) {
            const int n0 = (nt2 << 4) + g4;           // n row in [n][k] tile
            const int ib = n0 * PITCHW + kw;
            uint32_t bh0 = smw[oBh + ib];
            uint32_t bh1 = smw[oBh + ib + 4];
            uint32_t bh2 = smw[oBh + ib + 8 * PITCHW];
            uint32_t bh3 = smw[oBh + ib + 8 * PITCHW + 4];
            mma_bf16(acc[2 * nt2],     ah0, ah1, ah2, ah3, bh0, bh1);
            mma_bf16(acc[2 * nt2 + 1], ah0, ah1, ah2, ah3, bh2, bh3);
            mma_bf16(acc[2 * nt2],     al0, al1, al2, al3, bh0, bh1);
            mma_bf16(acc[2 * nt2 + 1], al0, al1, al2, al3, bh2, bh3);
            uint32_t bl0 = smw[oBl + ib];
            uint32_t bl1 = smw[oBl + ib + 4];
            uint32_t bl2 = smw[oBl + ib + 8 * PITCHW];
            uint32_t bl3 = smw[oBl + ib + 8 * PITCHW + 4];
            mma_bf16(acc[2 * nt2],     ah0, ah1, ah2, ah3, bl0, bl1);
            mma_bf16(acc[2 * nt2 + 1], ah0, ah1, ah2, ah3, bl2, bl3);
        }
    }
}

__global__ void __launch_bounds__(256, 1) gin_mlp_k(
    const float* x0, float* dout,
    const float* b1, const float* b2,
    int layer, int insel, int outsel)
{
    extern __shared__ __align__(16) __nv_bfloat16 sm[];
    __nv_bfloat16* sAh = sm;                 // tile 0
    __nv_bfloat16* sAl = sm + TILE_E;        // tile 1
    __nv_bfloat16* sW  = sm + 2 * TILE_E;    // tiles 2..5: W1hi, W1lo, W2hi, W2lo

    int tid = threadIdx.x, w = tid >> 5, l = tid & 31;
    long tile = (long)blockIdx.x * 128;

    const float* xres = sel_x(insel, x0);
    float* xout = (outsel == 3) ? dout : (outsel == 1 ? g_x1 : g_x2);
    const __nv_bfloat16* wt = g_w + (size_t)layer * 4 * HID * HID;

    // Load 4 weight tiles ([n][k] bf16) into pitched smem (16B chunks)
    for (int i = tid; i < 4 * 128 * 16; i += 256) {
        int t = i >> 11;
        int r = (i >> 4) & 127;
        int c = (i & 15) << 3;
        uint4 v = *reinterpret_cast<const uint4*>(wt + ((size_t)t << 14) + (r << 7) + c);
        *reinterpret_cast<uint4*>(sW + t * TILE_E + r * PITCH + c) = v;
    }

    // Load activation tile, split fp32 -> hi/lo bf16
    for (int i = tid; i < 128 * 16; i += 256) {
        int r = i >> 4;
        int c = (i & 15) << 3;
        long g = tile + r;
        float vv[8];
        if (g < N_NODES) {
            const float4* p = reinterpret_cast<const float4*>(g_out + g * HID + c);
            float4 v0 = p[0], v1 = p[1];
            vv[0] = v0.x; vv[1] = v0.y; vv[2] = v0.z; vv[3] = v0.w;
            vv[4] = v1.x; vv[5] = v1.y; vv[6] = v1.z; vv[7] = v1.w;
        } else {
            #pragma unroll
            for (int j = 0; j < 8; j++) vv[j] = 0.0f;
        }
        union { unsigned short s[8]; uint4 q; } ph, pl;
        #pragma unroll
        for (int j = 0; j < 8; j++) {
            __nv_bfloat16 h = __float2bfloat16(vv[j]);
            __nv_bfloat16 lo = __float2bfloat16(vv[j] - __bfloat162float(h));
            ph.s[j] = *reinterpret_cast<unsigned short*>(&h);
            pl.s[j] = *reinterpret_cast<unsigned short*>(&lo);
        }
        *reinterpret_cast<uint4*>(sAh + r * PITCH + c) = ph.q;
        *reinterpret_cast<uint4*>(sAl + r * PITCH + c) = pl.q;
    }
    __syncthreads();

    uint32_t* smw = reinterpret_cast<uint32_t*>(sm);  // plain: no const, no restrict

    float acc[16][4];
    #pragma unroll
    for (int i = 0; i < 16; i++)
        #pragma unroll
        for (int j = 0; j < 4; j++) acc[i][j] = 0.0f;

    // GEMM1: agg @ W1   (A = tiles 0/1, B = tiles 2/3)
    gemm128(acc, smw, 0, TILE_W, 2 * TILE_W, 3 * TILE_W, w, l);
    __syncthreads();  // all warps done reading sA before overwrite

    // Epilogue 1: h = relu(acc + b1) -> split back into sAh/sAl
    {
        int row0 = (w << 4) + (l >> 2);
        int cbase = (l & 3) << 1;
        #pragma unroll
        for (int nt = 0; nt < 16; nt++) {
            int col = (nt << 3) + cbase;
            float bb0 = b1[col], bb1 = b1[col + 1];
            float v0 = fmaxf(acc[nt][0] + bb0, 0.0f);
            float v1 = fmaxf(acc[nt][1] + bb1, 0.0f);
            float v2 = fmaxf(acc[nt][2] + bb0, 0.0f);
            float v3 = fmaxf(acc[nt][3] + bb1, 0.0f);
            __nv_bfloat16 h0 = __float2bfloat16(v0), h1 = __float2bfloat16(v1);
            __nv_bfloat16 h2 = __float2bfloat16(v2), h3 = __float2bfloat16(v3);
            __nv_bfloat16 l0 = __float2bfloat16(v0 - __bfloat162float(h0));
            __nv_bfloat16 l1 = __float2bfloat16(v1 - __bfloat162float(h1));
            __nv_bfloat16 l2 = __float2bfloat16(v2 - __bfloat162float(h2));
            __nv_bfloat16 l3 = __float2bfloat16(v3 - __bfloat162float(h3));
            smw[row0 * PITCHW + (col >> 1)] =
                (uint32_t)*reinterpret_cast<unsigned short*>(&h0) |
                ((uint32_t)*reinterpret_cast<unsigned short*>(&h1) << 16);
            smw[(row0 + 8) * PITCHW + (col >> 1)] =
                (uint32_t)*reinterpret_cast<unsigned short*>(&h2) |
                ((uint32_t)*reinterpret_cast<unsigned short*>(&h3) << 16);
            smw[TILE_W + row0 * PITCHW + (col >> 1)] =
                (uint32_t)*reinterpret_cast<unsigned short*>(&l0) |
                ((uint32_t)*reinterpret_cast<unsigned short*>(&l1) << 16);
            smw[TILE_W + (row0 + 8) * PITCHW + (col >> 1)] =
                (uint32_t)*reinterpret_cast<unsigned short*>(&l2) |
                ((uint32_t)*reinterpret_cast<unsigned short*>(&l3) << 16);
        }
    }
    __syncthreads();

    #pragma unroll
    for (int i = 0; i < 16; i++)
        #pragma unroll
        for (int j = 0; j < 4; j++) acc[i][j] = 0.0f;

    // GEMM2: h @ W2   (A = tiles 0/1, B = tiles 4/5)
    gemm128(acc, smw, 0, TILE_W, 4 * TILE_W, 5 * TILE_W, w, l);

    // Epilogue 2: x_out = x_in + relu(acc + b2)
    {
        int row0 = (w << 4) + (l >> 2);
        int cbase = (l & 3) << 1;
        long g0 = tile + row0;
        long g1 = g0 + 8;
        #pragma unroll
        for (int nt = 0; nt < 16; nt++) {
            int col = (nt << 3) + cbase;
            float bb0 = b2[col], bb1 = b2[col + 1];
            if (g0 < N_NODES) {
                float2 xr = *reinterpret_cast<const float2*>(xres + g0 * HID + col);
                float2 o;
                o.x = xr.x + fmaxf(acc[nt][0] + bb0, 0.0f);
                o.y = xr.y + fmaxf(acc[nt][1] + bb1, 0.0f);
                *reinterpret_cast<float2*>(xout + g0 * HID + col) = o;
            }
            if (g1 < N_NODES) {
                float2 xr = *reinterpret_cast<const float2*>(xres + g1 * HID + col);
                float2 o;
                o.x = xr.x + fmaxf(acc[nt][2] + bb0, 0.0f);
                o.y = xr.y + fmaxf(acc[nt][3] + bb1, 0.0f);
                *reinterpret_cast<float2*>(xout + g1 * HID + col) = o;
            }
        }
    }
}

// ---------------------------------------------------------------------------
// Launch
// ---------------------------------------------------------------------------
extern "C" void kernel_launch(void* const* d_in, const int* in_sizes, int n_in,
                              void* d_out, int out_size) {
    const float* x  = (const float*)d_in[0];
    const void*  ei = d_in[1];                 // int32 or int64, detected on device
    const float* W1 = (const float*)d_in[2];
    const float* b1 = (const float*)d_in[3];
    const float* W2 = (const float*)d_in[4];
    const float* b2 = (const float*)d_in[5];
    float* out = (float*)d_out;

    cudaFuncSetAttribute(gin_mlp_k, cudaFuncAttributeMaxDynamicSharedMemorySize, SM_TOTAL);

    // dtype detection + weight split + CSR build (once per call)
    gin_detect_k<<<1, 32>>>((const int*)ei);
    gin_prep_w<<<(N_LAYERS * 2 * HID * HID + 255) / 256, 256>>>(W1, W2);
    gin_zero_k<<<(N_NODES + 255) / 256, 256>>>();
    gin_hist_k<<<(N_EDGES + 255) / 256, 256>>>(ei);
    gin_scan_k<<<1, 1024>>>();
    gin_scatter_k<<<(N_EDGES + 255) / 256, 256>>>(ei);

    const int agg_blocks = (N_NODES * 32 + 255) / 256;
    const int mlp_blocks = (N_NODES + 127) / 128;

    // layer schedule: insel -> outsel:  x->g_x1, g_x1->g_x2, g_x2->g_x1, g_x1->d_out
    const int ins[N_LAYERS]  = {0, 1, 2, 1};
    const int outs[N_LAYERS] = {1, 2, 1, 3};

    for (int l = 0; l < N_LAYERS; l++) {
        gin_agg_k<<<agg_blocks, 256>>>(x, ins[l]);
        gin_mlp_k<<<mlp_blocks, 256, SM_TOTAL>>>(x, out,
                                                 b1 + l * HID, b2 + l * HID,
                                                 l, ins[l], outs[l]);
    }
}

// round 16
// speedup vs baseline: 1.5917x; 1.1661x over previous
#include <cuda_runtime.h>
#include <cuda_bf16.h>
#include <cstdint>

#define N_NODES 100000
#define N_EDGES 1600000
#define HID 128
#define N_LAYERS 4

// ---------------------------------------------------------------------------
// Scratch (static __device__ — no allocations allowed)
// ---------------------------------------------------------------------------
__device__ alignas(16) float g_out[(size_t)N_NODES * HID];   // agg + x per layer
__device__ alignas(16) float g_x1[(size_t)N_NODES * HID];    // ping
__device__ alignas(16) float g_x2[(size_t)N_NODES * HID];    // pong
__device__ int   g_rowptr[N_NODES + 1];
__device__ int   g_cursor[N_NODES];
__device__ int   g_srcs[N_EDGES];
__device__ int   g_is64;
// per layer: 4 bf16 tiles [n][k] (transposed weights): W1hi, W1lo, W2hi, W2lo
__device__ alignas(16) __nv_bfloat16 g_w[(size_t)N_LAYERS * 4 * HID * HID];

// ---------------------------------------------------------------------------
// Warp-level mma.sync on registers (register operands only).
// ---------------------------------------------------------------------------
__device__ __forceinline__ void mma_bf16(float* c,
                                         uint32_t a0, uint32_t a1, uint32_t a2, uint32_t a3,
                                         uint32_t b0, uint32_t b1) {
    asm volatile("mma.sync.aligned.m16n8k16.row.col.f32.bf16.bf16.f32 "
                 "{%0,%1,%2,%3},{%4,%5,%6,%7},{%8,%9},{%0,%1,%2,%3};"
                 : "+f"(c[0]), "+f"(c[1]), "+f"(c[2]), "+f"(c[3])
                 : "r"(a0), "r"(a1), "r"(a2), "r"(a3), "r"(b0), "r"(b1));
}

// ---------------------------------------------------------------------------
// Edge-index dtype detection (JAX x64-disabled silently yields int32).
// ---------------------------------------------------------------------------
__global__ void gin_detect_k(const int* ei32) {
    if (threadIdx.x == 0 && blockIdx.x == 0) {
        int zeros = 0;
        for (int i = 0; i < 256; i++)
            if (ei32[2 * i + 1] == 0) zeros++;
        g_is64 = (zeros > 200) ? 1 : 0;
    }
}

__device__ __forceinline__ int edge_val(const void* ei, long idx) {
    if (g_is64) return (int)((const long long*)ei)[idx];
    return ((const int*)ei)[idx];
}

// ---------------------------------------------------------------------------
// CSR build kernels (dst-sorted counting sort; no fp atomics anywhere)
// ---------------------------------------------------------------------------
__global__ void gin_zero_k() {
    int i = blockIdx.x * blockDim.x + threadIdx.x;
    if (i < N_NODES) g_cursor[i] = 0;
}

__global__ void gin_hist_k(const void* ei) {
    int e = blockIdx.x * blockDim.x + threadIdx.x;
    if (e < N_EDGES) {
        int d = edge_val(ei, (long)N_EDGES + e);
        if (d >= 0 && d < N_NODES) atomicAdd(&g_cursor[d], 1);
    }
}

__global__ void gin_scan_k() {
    const int T = 1024, SEG = (N_NODES + 1023) / 1024;  // 98
    __shared__ int part[T];
    int t = threadIdx.x;
    int s = 0;
    for (int j = 0; j < SEG; j++) {
        int i = t * SEG + j;
        if (i < N_NODES) s += g_cursor[i];
    }
    part[t] = s;
    __syncthreads();
    for (int off = 1; off < T; off <<= 1) {
        int v = (t >= off) ? part[t - off] : 0;
        __syncthreads();
        part[t] += v;
        __syncthreads();
    }
    int run = (t > 0) ? part[t - 1] : 0;
    for (int j = 0; j < SEG; j++) {
        int i = t * SEG + j;
        if (i < N_NODES) {
            int c = g_cursor[i];
            g_rowptr[i] = run;
            g_cursor[i] = run;
            run += c;
        }
    }
    if (t == T - 1) g_rowptr[N_NODES] = part[T - 1];
}

__global__ void gin_scatter_k(const void* ei) {
    int e = blockIdx.x * blockDim.x + threadIdx.x;
    if (e < N_EDGES) {
        int d = edge_val(ei, (long)N_EDGES + e);
        int s = edge_val(ei, e);
        if (d >= 0 && d < N_NODES && s >= 0 && s < N_NODES) {
            int pos = atomicAdd(&g_cursor[d], 1);
            if (pos >= 0 && pos < N_EDGES) g_srcs[pos] = s;
        }
    }
}

// ---------------------------------------------------------------------------
// Weight prep: split fp32 -> (hi, lo) bf16, transposed to [n][k]
// ---------------------------------------------------------------------------
__global__ void gin_prep_w(const float* W1, const float* W2) {
    int i = blockIdx.x * blockDim.x + threadIdx.x;
    if (i >= N_LAYERS * 2 * HID * HID) return;
    int l = i >> 15;          // 2*128*128 = 32768 per layer
    int m = (i >> 14) & 1;    // 0 = W1, 1 = W2
    int k = (i >> 7) & 127;   // input dim
    int n = i & 127;          // output dim
    float w = (m == 0 ? W1 : W2)[(size_t)l * HID * HID + k * HID + n];
    __nv_bfloat16 hi = __float2bfloat16(w);
    __nv_bfloat16 lo = __float2bfloat16(w - __bfloat162float(hi));
    size_t base = ((size_t)l * 4 + m * 2) * (HID * HID) + (size_t)n * HID + k;
    g_w[base] = hi;
    g_w[base + (size_t)HID * HID] = lo;
}

// ---------------------------------------------------------------------------
// Aggregation: identical to R15 (best variant): 4-wide pipelined shfl gather.
// ---------------------------------------------------------------------------
__device__ __forceinline__ const float* sel_x(int sel, const float* x0) {
    return sel == 0 ? x0 : (sel == 1 ? g_x1 : g_x2);
}

__global__ void gin_agg_k(const float* x0, int insel) {
    const float* x = sel_x(insel, x0);
    int node = (blockIdx.x * blockDim.x + threadIdx.x) >> 5;
    int lane = threadIdx.x & 31;
    if (node >= N_NODES) return;
    int beg = g_rowptr[node];
    int end = g_rowptr[node + 1];
    const float4* x4 = reinterpret_cast<const float4*>(x);
    float4 accA = x4[(size_t)node * 32 + lane];
    float4 accB = make_float4(0.f, 0.f, 0.f, 0.f);
    for (int j = beg; j < end; j += 32) {
        int n = end - j;
        if (n > 32) n = 32;
        int my = (lane < n) ? g_srcs[j + lane] : 0;
        int t = 0;
        for (; t + 4 <= n; t += 4) {
            int s0 = __shfl_sync(0xFFFFFFFFu, my, t);
            int s1 = __shfl_sync(0xFFFFFFFFu, my, t + 1);
            int s2 = __shfl_sync(0xFFFFFFFFu, my, t + 2);
            int s3 = __shfl_sync(0xFFFFFFFFu, my, t + 3);
            float4 v0 = x4[(size_t)s0 * 32 + lane];
            float4 v1 = x4[(size_t)s1 * 32 + lane];
            float4 v2 = x4[(size_t)s2 * 32 + lane];
            float4 v3 = x4[(size_t)s3 * 32 + lane];
            accA.x += v0.x; accA.y += v0.y; accA.z += v0.z; accA.w += v0.w;
            accB.x += v1.x; accB.y += v1.y; accB.z += v1.z; accB.w += v1.w;
            accA.x += v2.x; accA.y += v2.y; accA.z += v2.z; accA.w += v2.w;
            accB.x += v3.x; accB.y += v3.y; accB.z += v3.z; accB.w += v3.w;
        }
        for (; t < n; t++) {
            int s = __shfl_sync(0xFFFFFFFFu, my, t);
            float4 v = x4[(size_t)s * 32 + lane];
            accA.x += v.x; accA.y += v.y; accA.z += v.z; accA.w += v.w;
        }
    }
    accA.x += accB.x; accA.y += accB.y; accA.z += accB.z; accA.w += accB.w;
    reinterpret_cast<float4*>(g_out)[(size_t)node * 32 + lane] = accA;
}

// ---------------------------------------------------------------------------
// Fused MLP with W-slice streaming for 2 CTAs/SM (16 warps/SM).
// smem: A hi/lo tiles (PITCH 136) + double-buffered 16-k W slices
// (128 n x 24 bf16, pitch 12 words -> conflict-free fragment loads).
// ---------------------------------------------------------------------------
#define PITCH 136
#define PITCHW 68
#define TILE_E (128 * PITCH)         // bf16 elems per A tile
#define TILE_W (TILE_E / 2)          // words per A tile (8704)
#define SLICE_PW 12                  // words per slice row (24 bf16, 8 used + 4 pad)
#define SLICE_TW (128 * SLICE_PW)    // words per slice tile (1536)
#define O_S (2 * TILE_W)             // word offset of slice buffers
#define SM_TOTAL ((O_S + 4 * SLICE_TW) * 4)   // 94208 bytes

// one k-step (16 k) of the 3-term split-bf16 GEMM
__device__ __forceinline__ void gemm_step(float (*acc)[4], uint32_t* smw,
                                          int oSh, int oSl, int k0, int w, int l) {
    const int g4 = l >> 2;
    const int t4 = l & 3;
    const int rowA = (w << 4) + g4;
    const int kw = (k0 << 3) + t4;
    const int ia = rowA * PITCHW + kw;
    uint32_t ah0 = smw[ia];
    uint32_t ah1 = smw[ia + 8 * PITCHW];
    uint32_t ah2 = smw[ia + 4];
    uint32_t ah3 = smw[ia + 8 * PITCHW + 4];
    uint32_t al0 = smw[TILE_W + ia];
    uint32_t al1 = smw[TILE_W + ia + 8 * PITCHW];
    uint32_t al2 = smw[TILE_W + ia + 4];
    uint32_t al3 = smw[TILE_W + ia + 8 * PITCHW + 4];
    #pragma unroll
    for (int nt2 = 0; nt2 < 8; nt2++) {
        const int n0 = (nt2 << 4) + g4;
        const int ib = n0 * SLICE_PW + t4;
        uint32_t bh0 = smw[oSh + ib];
        uint32_t bh1 = smw[oSh + ib + 4];
        uint32_t bh2 = smw[oSh + ib + 8 * SLICE_PW];
        uint32_t bh3 = smw[oSh + ib + 8 * SLICE_PW + 4];
        mma_bf16(acc[2 * nt2],     ah0, ah1, ah2, ah3, bh0, bh1);
        mma_bf16(acc[2 * nt2 + 1], ah0, ah1, ah2, ah3, bh2, bh3);
        mma_bf16(acc[2 * nt2],     al0, al1, al2, al3, bh0, bh1);
        mma_bf16(acc[2 * nt2 + 1], al0, al1, al2, al3, bh2, bh3);
        uint32_t bl0 = smw[oSl + ib];
        uint32_t bl1 = smw[oSl + ib + 4];
        uint32_t bl2 = smw[oSl + ib + 8 * SLICE_PW];
        uint32_t bl3 = smw[oSl + ib + 8 * SLICE_PW + 4];
        mma_bf16(acc[2 * nt2],     ah0, ah1, ah2, ah3, bl0, bl1);
        mma_bf16(acc[2 * nt2 + 1], ah0, ah1, ah2, ah3, bl2, bl3);
    }
}

__global__ void __launch_bounds__(256, 2) gin_mlp_k(
    const float* x0, float* dout,
    const float* b1, const float* b2,
    int layer, int insel, int outsel)
{
    extern __shared__ __align__(16) __nv_bfloat16 sm[];
    __nv_bfloat16* sAh = sm;

    int tid = threadIdx.x, w = tid >> 5, l = tid & 31;
    long tile = (long)blockIdx.x * 128;

    const float* xres = sel_x(insel, x0);
    float* xout = (outsel == 3) ? dout : (outsel == 1 ? g_x1 : g_x2);
    const __nv_bfloat16* wt = g_w + (size_t)layer * 4 * HID * HID;

    uint32_t* smw = reinterpret_cast<uint32_t*>(sm);
    const int srow = tid >> 1;       // slice row handled by this thread
    const int shalf = tid & 1;       // which 8-elem half

    // Load activation tile, split fp32 -> hi/lo bf16 (tiles 0/1)
    for (int i = tid; i < 128 * 16; i += 256) {
        int r = i >> 4;
        int c = (i & 15) << 3;
        long g = tile + r;
        float vv[8];
        if (g < N_NODES) {
            const float4* p = reinterpret_cast<const float4*>(g_out + g * HID + c);
            float4 v0 = p[0], v1 = p[1];
            vv[0] = v0.x; vv[1] = v0.y; vv[2] = v0.z; vv[3] = v0.w;
            vv[4] = v1.x; vv[5] = v1.y; vv[6] = v1.z; vv[7] = v1.w;
        } else {
            #pragma unroll
            for (int j = 0; j < 8; j++) vv[j] = 0.0f;
        }
        union { unsigned short s[8]; uint4 q; } ph, pl;
        #pragma unroll
        for (int j = 0; j < 8; j++) {
            __nv_bfloat16 h = __float2bfloat16(vv[j]);
            __nv_bfloat16 lo = __float2bfloat16(vv[j] - __bfloat162float(h));
            ph.s[j] = *reinterpret_cast<unsigned short*>(&h);
            pl.s[j] = *reinterpret_cast<unsigned short*>(&lo);
        }
        *reinterpret_cast<uint4*>(sAh + r * PITCH + c) = ph.q;
        *reinterpret_cast<uint4*>(sAh + TILE_E + r * PITCH + c) = pl.q;
    }

    // Prologue: stage W1 slice k0=0 into buffer 0
    {
        uint4 rh = *reinterpret_cast<const uint4*>(wt + 0 * 16384 + srow * 128 + shalf * 8);
        uint4 rl = *reinterpret_cast<const uint4*>(wt + 1 * 16384 + srow * 128 + shalf * 8);
        *reinterpret_cast<uint4*>(smw + O_S + srow * SLICE_PW + shalf * 4) = rh;
        *reinterpret_cast<uint4*>(smw + O_S + SLICE_TW + srow * SLICE_PW + shalf * 4) = rl;
    }
    __syncthreads();

    float acc[16][4];
    #pragma unroll
    for (int i = 0; i < 16; i++)
        #pragma unroll
        for (int j = 0; j < 4; j++) acc[i][j] = 0.0f;

    // GEMM1: agg @ W1, streaming slices; prefetch next slice per step
    #pragma unroll
    for (int k0 = 0; k0 < 8; k0++) {
        int p = k0 & 1;
        // prefetch: next W1 slice, or W2 slice 0 on the last step
        int nt_tile = (k0 < 7) ? 0 : 2;
        int nt_k = (k0 < 7) ? (k0 + 1) : 0;
        uint4 rh = *reinterpret_cast<const uint4*>(wt + nt_tile * 16384 + srow * 128 + nt_k * 16 + shalf * 8);
        uint4 rl = *reinterpret_cast<const uint4*>(wt + (nt_tile + 1) * 16384 + srow * 128 + nt_k * 16 + shalf * 8);
        gemm_step(acc, smw, O_S + (p * 2) * SLICE_TW, O_S + (p * 2 + 1) * SLICE_TW, k0, w, l);
        int q = (k0 + 1) & 1;
        *reinterpret_cast<uint4*>(smw + O_S + (q * 2) * SLICE_TW + srow * SLICE_PW + shalf * 4) = rh;
        *reinterpret_cast<uint4*>(smw + O_S + (q * 2 + 1) * SLICE_TW + srow * SLICE_PW + shalf * 4) = rl;
        __syncthreads();
    }

    // Epilogue 1: h = relu(acc + b1) -> split back into A tiles
    {
        int row0 = (w << 4) + (l >> 2);
        int cbase = (l & 3) << 1;
        #pragma unroll
        for (int nt = 0; nt < 16; nt++) {
            int col = (nt << 3) + cbase;
            float bb0 = b1[col], bb1 = b1[col + 1];
            float v0 = fmaxf(acc[nt][0] + bb0, 0.0f);
            float v1 = fmaxf(acc[nt][1] + bb1, 0.0f);
            float v2 = fmaxf(acc[nt][2] + bb0, 0.0f);
            float v3 = fmaxf(acc[nt][3] + bb1, 0.0f);
            __nv_bfloat16 h0 = __float2bfloat16(v0), h1 = __float2bfloat16(v1);
            __nv_bfloat16 h2 = __float2bfloat16(v2), h3 = __float2bfloat16(v3);
            __nv_bfloat16 l0 = __float2bfloat16(v0 - __bfloat162float(h0));
            __nv_bfloat16 l1 = __float2bfloat16(v1 - __bfloat162float(h1));
            __nv_bfloat16 l2 = __float2bfloat16(v2 - __bfloat162float(h2));
            __nv_bfloat16 l3 = __float2bfloat16(v3 - __bfloat162float(h3));
            smw[row0 * PITCHW + (col >> 1)] =
                (uint32_t)*reinterpret_cast<unsigned short*>(&h0) |
                ((uint32_t)*reinterpret_cast<unsigned short*>(&h1) << 16);
            smw[(row0 + 8) * PITCHW + (col >> 1)] =
                (uint32_t)*reinterpret_cast<unsigned short*>(&h2) |
                ((uint32_t)*reinterpret_cast<unsigned short*>(&h3) << 16);
            smw[TILE_W + row0 * PITCHW + (col >> 1)] =
                (uint32_t)*reinterpret_cast<unsigned short*>(&l0) |
                ((uint32_t)*reinterpret_cast<unsigned short*>(&l1) << 16);
            smw[TILE_W + (row0 + 8) * PITCHW + (col >> 1)] =
                (uint32_t)*reinterpret_cast<unsigned short*>(&l2) |
                ((uint32_t)*reinterpret_cast<unsigned short*>(&l3) << 16);
        }
    }
    __syncthreads();

    #pragma unroll
    for (int i = 0; i < 16; i++)
        #pragma unroll
        for (int j = 0; j < 4; j++) acc[i][j] = 0.0f;

    // GEMM2: h @ W2 (W2 slice 0 already resident in buffer 0)
    #pragma unroll
    for (int k0 = 0; k0 < 8; k0++) {
        int p = k0 & 1;
        uint4 rh, rl;
        if (k0 < 7) {
            rh = *reinterpret_cast<const uint4*>(wt + 2 * 16384 + srow * 128 + (k0 + 1) * 16 + shalf * 8);
            rl = *reinterpret_cast<const uint4*>(wt + 3 * 16384 + srow * 128 + (k0 + 1) * 16 + shalf * 8);
        }
        gemm_step(acc, smw, O_S + (p * 2) * SLICE_TW, O_S + (p * 2 + 1) * SLICE_TW, k0, w, l);
        if (k0 < 7) {
            int q = (k0 + 1) & 1;
            *reinterpret_cast<uint4*>(smw + O_S + (q * 2) * SLICE_TW + srow * SLICE_PW + shalf * 4) = rh;
            *reinterpret_cast<uint4*>(smw + O_S + (q * 2 + 1) * SLICE_TW + srow * SLICE_PW + shalf * 4) = rl;
            __syncthreads();
        }
    }

    // Epilogue 2: x_out = x_in + relu(acc + b2)  (no smem use)
    {
        int row0 = (w << 4) + (l >> 2);
        int cbase = (l & 3) << 1;
        long g0 = tile + row0;
        long g1 = g0 + 8;
        #pragma unroll
        for (int nt = 0; nt < 16; nt++) {
            int col = (nt << 3) + cbase;
            float bb0 = b2[col], bb1 = b2[col + 1];
            if (g0 < N_NODES) {
                float2 xr = *reinterpret_cast<const float2*>(xres + g0 * HID + col);
                float2 o;
                o.x = xr.x + fmaxf(acc[nt][0] + bb0, 0.0f);
                o.y = xr.y + fmaxf(acc[nt][1] + bb1, 0.0f);
                *reinterpret_cast<float2*>(xout + g0 * HID + col) = o;
            }
            if (g1 < N_NODES) {
                float2 xr = *reinterpret_cast<const float2*>(xres + g1 * HID + col);
                float2 o;
                o.x = xr.x + fmaxf(acc[nt][2] + bb0, 0.0f);
                o.y = xr.y + fmaxf(acc[nt][3] + bb1, 0.0f);
                *reinterpret_cast<float2*>(xout + g1 * HID + col) = o;
            }
        }
    }
}

// ---------------------------------------------------------------------------
// Launch
// ---------------------------------------------------------------------------
extern "C" void kernel_launch(void* const* d_in, const int* in_sizes, int n_in,
                              void* d_out, int out_size) {
    const float* x  = (const float*)d_in[0];
    const void*  ei = d_in[1];                 // int32 or int64, detected on device
    const float* W1 = (const float*)d_in[2];
    const float* b1 = (const float*)d_in[3];
    const float* W2 = (const float*)d_in[4];
    const float* b2 = (const float*)d_in[5];
    float* out = (float*)d_out;

    cudaFuncSetAttribute(gin_mlp_k, cudaFuncAttributeMaxDynamicSharedMemorySize, SM_TOTAL);

    // dtype detection + weight split + CSR build (once per call)
    gin_detect_k<<<1, 32>>>((const int*)ei);
    gin_prep_w<<<(N_LAYERS * 2 * HID * HID + 255) / 256, 256>>>(W1, W2);
    gin_zero_k<<<(N_NODES + 255) / 256, 256>>>();
    gin_hist_k<<<(N_EDGES + 255) / 256, 256>>>(ei);
    gin_scan_k<<<1, 1024>>>();
    gin_scatter_k<<<(N_EDGES + 255) / 256, 256>>>(ei);

    const int agg_blocks = (N_NODES * 32 + 255) / 256;
    const int mlp_blocks = (N_NODES + 127) / 128;

    // layer schedule: insel -> outsel:  x->g_x1, g_x1->g_x2, g_x2->g_x1, g_x1->d_out
    const int ins[N_LAYERS]  = {0, 1, 2, 1};
    const int outs[N_LAYERS] = {1, 2, 1, 3};

    for (int l = 0; l < N_LAYERS; l++) {
        gin_agg_k<<<agg_blocks, 256>>>(x, ins[l]);
        gin_mlp_k<<<mlp_blocks, 256, SM_TOTAL>>>(x, out,
                                                 b1 + l * HID, b2 + l * HID,
                                                 l, ins[l], outs[l]);
    }
}